// round 7
// baseline (speedup 1.0000x reference)
#include <cuda_runtime.h>
#include <math.h>

// ---------------------------------------------------------------------------
// SphereIBSDE: 100-step sphere SDE with per-step MLP (96->256->256->96),
// global active-row compaction, f32x2 packed-FMA GEMMs (16 rows per block).
// Graph: prologue + 100 step kernels + epilogue (all fixed grids).
// ---------------------------------------------------------------------------

#define BN      4096
#define DXN     32
#define D3N     96
#define NSTEPN  100
#define HN      256
#define MROWS   16
#define NBLK    (BN / MROWS)       // 256
#define NTHR    256
#define XSTR    16                 // s_x stride: s_x[k*16 + m]
#define HSTR    20                 // hidden stride (16B-aligned rows)
#define HIT_EPSF 0.05f
#define CLIPF   (1.0f - 1e-6f)
#define PI_HALF 1.57079632679489662f

// persistent scratch (static device globals; no allocation)
__device__ float g_xt[BN * D3N];
__device__ float g_p[BN];
__device__ int   g_list[2][BN];
__device__ int   g_cnts[NSTEPN + 1];

// ---- packed f32x2 helpers ---------------------------------------------------
__device__ __forceinline__ unsigned long long pk2(float x, float y) {
    unsigned long long r;
    asm("mov.b64 %0, {%1, %2};" : "=l"(r) : "f"(x), "f"(y));
    return r;
}
__device__ __forceinline__ void upk2(unsigned long long v, float& x, float& y) {
    asm("mov.b64 {%0, %1}, %2;" : "=f"(x), "=f"(y) : "l"(v));
}
__device__ __forceinline__ unsigned long long ffma2(unsigned long long a,
                                                    unsigned long long b,
                                                    unsigned long long c) {
    unsigned long long d;
    asm("fma.rn.f32x2 %0, %1, %2, %3;" : "=l"(d) : "l"(a), "l"(b), "l"(c));
    return d;
}

// ---- dense accumulate: 16 rows, one output column (c) per calling thread ----
// W is [K][WSTR] row-major. sIn is transposed smem [K][INSTR], rows in low 16.
// acc[i] holds packed rows (2i, 2i+1).
template <int K0, int K1, int INSTR, int WSTR>
__device__ __forceinline__ void dense_acc(const float* __restrict__ W,
                                          const float* sIn, int c,
                                          unsigned long long acc[8]) {
#pragma unroll
    for (int i = 0; i < 8; i++) acc[i] = 0ULL;
#pragma unroll 4
    for (int k = K0; k < K1; k++) {
        float w = W[(size_t)k * WSTR + c];
        unsigned long long ww = pk2(w, w);
        const ulonglong2* xp = reinterpret_cast<const ulonglong2*>(sIn + k * INSTR);
        ulonglong2 a0 = xp[0];
        ulonglong2 a1 = xp[1];
        ulonglong2 a2 = xp[2];
        ulonglong2 a3 = xp[3];
        acc[0] = ffma2(a0.x, ww, acc[0]);
        acc[1] = ffma2(a0.y, ww, acc[1]);
        acc[2] = ffma2(a1.x, ww, acc[2]);
        acc[3] = ffma2(a1.y, ww, acc[3]);
        acc[4] = ffma2(a2.x, ww, acc[4]);
        acc[5] = ffma2(a2.y, ww, acc[5]);
        acc[6] = ffma2(a3.x, ww, acc[6]);
        acc[7] = ffma2(a3.y, ww, acc[7]);
    }
}

// ---------------------------------------------------------------------------
// Prologue: p0 = pMLP(x0), copy x0 -> g_xt, init work list / counters.
// ---------------------------------------------------------------------------
__global__ __launch_bounds__(NTHR) void sibsde_prologue(
    const float* __restrict__ x0,
    const float* __restrict__ pW1, const float* __restrict__ pb1,
    const float* __restrict__ pW2, const float* __restrict__ pb2,
    const float* __restrict__ pW3, const float* __restrict__ pb3) {
    __shared__ __align__(16) float s_x[D3N * XSTR];
    __shared__ __align__(16) float s_h1[HN * HSTR];
    __shared__ __align__(16) float s_h2[HN * HSTR];

    const int tid = threadIdx.x;
    const int base0 = blockIdx.x * MROWS;

    for (int idx = tid; idx < MROWS * D3N; idx += NTHR) {
        int m = idx / D3N;
        int k = idx - m * D3N;
        float v = x0[(size_t)(base0 + m) * D3N + k];
        g_xt[(size_t)(base0 + m) * D3N + k] = v;
        s_x[k * XSTR + m] = v;
    }
    __syncthreads();

    {   // layer 1: 96 -> 256, tanh
        unsigned long long acc[8];
        dense_acc<0, D3N, XSTR, HN>(pW1, s_x, tid, acc);
        float bv = pb1[tid];
#pragma unroll
        for (int i = 0; i < 8; i++) {
            float u, v; upk2(acc[i], u, v);
            s_h1[tid * HSTR + 2 * i]     = tanhf(u + bv);
            s_h1[tid * HSTR + 2 * i + 1] = tanhf(v + bv);
        }
    }
    __syncthreads();
    {   // layer 2: 256 -> 256, tanh
        unsigned long long acc[8];
        dense_acc<0, HN, HSTR, HN>(pW2, s_h1, tid, acc);
        float bv = pb2[tid];
#pragma unroll
        for (int i = 0; i < 8; i++) {
            float u, v; upk2(acc[i], u, v);
            s_h2[tid * HSTR + 2 * i]     = tanhf(u + bv);
            s_h2[tid * HSTR + 2 * i + 1] = tanhf(v + bv);
        }
    }
    __syncthreads();

    // scalar head: p0[m] = h2[:,m] . pW3 + pb3; warp w handles rows 2w, 2w+1
    const int w = tid >> 5, lane = tid & 31;
#pragma unroll
    for (int r = 0; r < 2; r++) {
        int m = 2 * w + r;
        float s = 0.0f;
#pragma unroll
        for (int j = 0; j < 8; j++) {
            int k = lane + 32 * j;
            s += s_h2[k * HSTR + m] * pW3[k];
        }
#pragma unroll
        for (int o = 16; o > 0; o >>= 1) s += __shfl_xor_sync(0xffffffffu, s, o);
        if (lane == 0) g_p[base0 + m] = s + pb3[0];
    }

    if (tid < MROWS) g_list[0][base0 + tid] = base0 + tid;
    if (blockIdx.x == 0 && tid <= NSTEPN) g_cnts[tid] = (tid == 0) ? BN : 0;
}

// ---------------------------------------------------------------------------
// Step t: grad = gMLP_t(xt) for active rows; geometry + p update; hit
// detection; survivor compaction into the next list.
// ---------------------------------------------------------------------------
__global__ __launch_bounds__(NTHR) void sibsde_step(
    int t,
    const float* __restrict__ dBt, const float* __restrict__ D,
    const float* __restrict__ gW1, const float* __restrict__ gb1,
    const float* __restrict__ gW2, const float* __restrict__ gb2,
    const float* __restrict__ gW3, const float* __restrict__ gb3,
    float* __restrict__ out) {
    __shared__ __align__(16) float s_x[D3N * XSTR];     // reused as layer3 partial-2
    __shared__ __align__(16) float s_h1[HN * HSTR];     // reused as layer3 partial-1
    __shared__ __align__(16) float s_h2[HN * HSTR];
    __shared__ int   s_rows[MROWS];
    __shared__ float s_sD[DXN];

    const int cnt = g_cnts[t];
    const int base0 = blockIdx.x * MROWS;
    if (base0 >= cnt) return;
    const int nact = min(MROWS, cnt - base0);
    const int tid = threadIdx.x;
    const int pin = t & 1, pout = pin ^ 1;

    if (tid < MROWS) s_rows[tid] = (tid < nact) ? g_list[pin][base0 + tid] : 0;
    if (tid < DXN)   s_sD[tid] = sqrtf(2.0f * D[tid]) * 0.1f;   // sqrt(2D)*sqrt(dt)
    __syncthreads();

    for (int idx = tid; idx < MROWS * D3N; idx += NTHR) {
        int m = idx / D3N;
        int k = idx - m * D3N;
        float v = (m < nact) ? g_xt[(size_t)s_rows[m] * D3N + k] : 0.0f;
        s_x[k * XSTR + m] = v;
    }
    __syncthreads();

    const float* W1 = gW1 + (size_t)t * D3N * HN;
    const float* b1 = gb1 + (size_t)t * HN;
    const float* W2 = gW2 + (size_t)t * HN * HN;
    const float* b2 = gb2 + (size_t)t * HN;
    const float* W3 = gW3 + (size_t)t * HN * D3N;
    const float* b3 = gb3 + (size_t)t * D3N;

    {   // layer 1: 96 -> 256, tanh
        unsigned long long acc[8];
        dense_acc<0, D3N, XSTR, HN>(W1, s_x, tid, acc);
        float bv = b1[tid];
#pragma unroll
        for (int i = 0; i < 8; i++) {
            float u, v; upk2(acc[i], u, v);
            s_h1[tid * HSTR + 2 * i]     = tanhf(u + bv);
            s_h1[tid * HSTR + 2 * i + 1] = tanhf(v + bv);
        }
    }
    __syncthreads();
    {   // layer 2: 256 -> 256, tanh
        unsigned long long acc[8];
        dense_acc<0, HN, HSTR, HN>(W2, s_h1, tid, acc);
        float bv = b2[tid];
#pragma unroll
        for (int i = 0; i < 8; i++) {
            float u, v; upk2(acc[i], u, v);
            s_h2[tid * HSTR + 2 * i]     = tanhf(u + bv);
            s_h2[tid * HSTR + 2 * i + 1] = tanhf(v + bv);
        }
    }
    __syncthreads();

    // layer 3 (256 -> 96, no activation), split-K across two thread groups.
    // Partial 1 (k in [0,128), +bias) -> s_g (overlays s_h1, dead).
    // Partial 2 (k in [128,256))      -> s_pg2 (overlays s_x, dead).
    float* s_g   = s_h1;   // [MROWS][96] compact
    float* s_pg2 = s_x;    // [MROWS][96] compact
    if (tid < D3N) {
        unsigned long long acc[8];
        dense_acc<0, HN / 2, HSTR, D3N>(W3, s_h2, tid, acc);
        float bv = b3[tid];
#pragma unroll
        for (int i = 0; i < 8; i++) {
            float u, v; upk2(acc[i], u, v);
            s_g[(2 * i) * D3N + tid]     = u + bv;
            s_g[(2 * i + 1) * D3N + tid] = v + bv;
        }
    } else if (tid >= 128 && tid < 128 + D3N) {
        int c = tid - 128;
        unsigned long long acc[8];
        dense_acc<HN / 2, HN, HSTR, D3N>(W3, s_h2, c, acc);
#pragma unroll
        for (int i = 0; i < 8; i++) {
            float u, v; upk2(acc[i], u, v);
            s_pg2[(2 * i) * D3N + c]     = u;
            s_pg2[(2 * i + 1) * D3N + c] = v;
        }
    }
    __syncthreads();

    // ---- geometry + p update: warp w owns rows 2w, 2w+1; lane = sphere point
    const int w = tid >> 5, lane = tid & 31;
#pragma unroll
    for (int r = 0; r < 2; r++) {
        int m = 2 * w + r;
        if (m >= nact) continue;
        int b = s_rows[m];
        float* xr = g_xt + (size_t)b * D3N;
        float x = xr[3 * lane + 0];
        float y = xr[3 * lane + 1];
        float z = xr[3 * lane + 2];

        // theta = acos(clip(z)); a = theta - pi/2 => sin(a) = -zc, cos(a) = sqrt(1-zc^2)
        float zc = fminf(fmaxf(z, -CLIPF), CLIPF);
        float sa = -zc;
        float ca = sqrtf(fmaxf(1.0f - zc * zc, 0.0f));
        // phi = atan2(y, x) => cos = x/hyp, sin = y/hyp (atan2(0,0)=0 -> cp=1, sp=0)
        float hyp = sqrtf(x * x + y * y);
        float cp, sp;
        if (hyp > 0.0f) { cp = x / hyp; sp = y / hyp; }
        else            { cp = 1.0f;    sp = 0.0f;    }

        float2 dv = reinterpret_cast<const float2*>(dBt)
                        [((size_t)t * BN + b) * DXN + lane];
        float dth = s_sD[lane] * dv.x;
        float dph = s_sD[lane] * dv.y;

        float th = dth + PI_HALF;
        float sth, cth; sincosf(th,  &sth, &cth);
        float sph, cph; sincosf(dph, &sph, &cph);
        float e0  = sth * cph - 1.0f;
        float e1  = sth * sph;
        float e2v = cth;

        float d0 = cp * ca * e0 - sp * e1 + cp * sa * e2v;
        float d1 = sp * ca * e0 + cp * e1 + sp * sa * e2v;
        float d2 = -sa * e0 + ca * e2v;

        float xn = x + d0;
        float yn = y + d1;
        float zn = z + d2;
        zn = fabsf(zn);                       // reflect: where(z<0, -z, z)

        xr[3 * lane + 0] = xn;
        xr[3 * lane + 1] = yn;
        xr[3 * lane + 2] = zn;

        // gradient rotation -> dp contribution
        float g0 = s_g[m * D3N + 3 * lane + 0] + s_pg2[m * D3N + 3 * lane + 0];
        float g1 = s_g[m * D3N + 3 * lane + 1] + s_pg2[m * D3N + 3 * lane + 1];
        float g2 = s_g[m * D3N + 3 * lane + 2] + s_pg2[m * D3N + 3 * lane + 2];
        float r1v = -g0 * sp + g1 * cp;
        float r2v = g0 * cp * sa + g1 * sp * sa + g2 * ca;
        float dpl = -r2v * dth + r1v * dph;   // gp2 . dpolar
        float xs  = xn + yn + zn;             // for p_rel mean

        unsigned hm = __ballot_sync(0xffffffffu, zn < HIT_EPSF);
#pragma unroll
        for (int o = 16; o > 0; o >>= 1) {
            dpl += __shfl_xor_sync(0xffffffffu, dpl, o);
            xs  += __shfl_xor_sync(0xffffffffu, xs,  o);
        }
        if (lane == 0) {
            float pold = g_p[b];
            float pnew = pold + (-(0.2f * pold) * 0.01f + dpl);
            if (hm) {   // hit this step: finalize output for this row
                reinterpret_cast<float2*>(out)[b] = make_float2(pnew, xs / 96.0f);
            } else {    // survivor: carry p, append to next list
                g_p[b] = pnew;
                int pos = atomicAdd(&g_cnts[t + 1], 1);
                g_list[pout][pos] = b;
            }
        }
    }
}

// ---------------------------------------------------------------------------
// Epilogue: rows still running after 100 steps -> out = {p, mean(xt)}.
// ---------------------------------------------------------------------------
__global__ __launch_bounds__(NTHR) void sibsde_epilogue(float* __restrict__ out) {
    const int cnt = g_cnts[NSTEPN];
    const int wi = (blockIdx.x * NTHR + threadIdx.x) >> 5;
    const int lane = threadIdx.x & 31;
    if (wi >= cnt) return;
    int b = g_list[NSTEPN & 1][wi];
    const float* xr = g_xt + (size_t)b * D3N;
    float s = xr[lane] + xr[lane + 32] + xr[lane + 64];
#pragma unroll
    for (int o = 16; o > 0; o >>= 1) s += __shfl_xor_sync(0xffffffffu, s, o);
    if (lane == 0)
        reinterpret_cast<float2*>(out)[b] = make_float2(g_p[b], s / 96.0f);
}

// ---------------------------------------------------------------------------
extern "C" void kernel_launch(void* const* d_in, const int* in_sizes, int n_in,
                              void* d_out, int out_size) {
    const float* x0  = (const float*)d_in[0];
    const float* dBt = (const float*)d_in[1];
    const float* D   = (const float*)d_in[2];
    const float* pW1 = (const float*)d_in[3];
    const float* pb1 = (const float*)d_in[4];
    const float* pW2 = (const float*)d_in[5];
    const float* pb2 = (const float*)d_in[6];
    const float* pW3 = (const float*)d_in[7];
    const float* pb3 = (const float*)d_in[8];
    const float* gW1 = (const float*)d_in[9];
    const float* gb1 = (const float*)d_in[10];
    const float* gW2 = (const float*)d_in[11];
    const float* gb2 = (const float*)d_in[12];
    const float* gW3 = (const float*)d_in[13];
    const float* gb3 = (const float*)d_in[14];
    float* out = (float*)d_out;

    sibsde_prologue<<<NBLK, NTHR>>>(x0, pW1, pb1, pW2, pb2, pW3, pb3);
    for (int t = 0; t < NSTEPN; t++)
        sibsde_step<<<NBLK, NTHR>>>(t, dBt, D, gW1, gb1, gW2, gb2, gW3, gb3, out);
    sibsde_epilogue<<<BN * 32 / NTHR, NTHR>>>(out);
}

// round 8
// speedup vs baseline: 1.5346x; 1.5346x over previous
#include <cuda_runtime.h>
#include <math.h>

// ---------------------------------------------------------------------------
// SphereIBSDE: 100-step sphere SDE with per-step MLP (96->256->256->96).
// Step 0: full batch, 16-row tiles (FFMA2-efficient).
// Steps 1..99: fused windows (1,2,4,8,...) of 4-row blocks with local row
// retention; global compaction at window boundaries only.
// Graph: prologue + step0 + 15 fused windows + epilogue = 18 nodes.
// ---------------------------------------------------------------------------

#define BN      4096
#define DXN     32
#define D3N     96
#define NSTEPN  100
#define HN      256
#define MROWS   16
#define NBLK    (BN / MROWS)       // 256
#define NTHR    256
#define XSTR    16                 // step16 s_x stride
#define HSTR    20                 // step16 hidden stride
#define HIT_EPSF 0.05f
#define CLIPF   (1.0f - 1e-6f)
#define PI_HALF 1.57079632679489662f

// persistent scratch (static device globals; no allocation)
__device__ float g_xt[BN * D3N];
__device__ float g_p[BN];
__device__ int   g_list[2][BN];
__device__ int   g_wcnt[32];       // checkpoint counters (17 used)

// ---- packed f32x2 helpers ---------------------------------------------------
__device__ __forceinline__ unsigned long long pk2(float x, float y) {
    unsigned long long r;
    asm("mov.b64 %0, {%1, %2};" : "=l"(r) : "f"(x), "f"(y));
    return r;
}
__device__ __forceinline__ void upk2(unsigned long long v, float& x, float& y) {
    asm("mov.b64 {%0, %1}, %2;" : "=f"(x), "=f"(y) : "l"(v));
}
__device__ __forceinline__ unsigned long long ffma2(unsigned long long a,
                                                    unsigned long long b,
                                                    unsigned long long c) {
    unsigned long long d;
    asm("fma.rn.f32x2 %0, %1, %2, %3;" : "=l"(d) : "l"(a), "l"(b), "l"(c));
    return d;
}

// fast tanh: only feeds p (never the xt / hit path), so approx is safe.
__device__ __forceinline__ float ftanh(float x) {
    float e = __expf(2.0f * x);
    return 1.0f - __fdividef(2.0f, e + 1.0f);
}

// ---- 16-row dense accumulate (step0 / prologue) ------------------------------
template <int K0, int K1, int INSTR, int WSTR>
__device__ __forceinline__ void dense_acc(const float* __restrict__ W,
                                          const float* sIn, int c,
                                          unsigned long long acc[8]) {
#pragma unroll
    for (int i = 0; i < 8; i++) acc[i] = 0ULL;
#pragma unroll 4
    for (int k = K0; k < K1; k++) {
        float w = W[(size_t)k * WSTR + c];
        unsigned long long ww = pk2(w, w);
        const ulonglong2* xp = reinterpret_cast<const ulonglong2*>(sIn + k * INSTR);
        ulonglong2 a0 = xp[0];
        ulonglong2 a1 = xp[1];
        ulonglong2 a2 = xp[2];
        ulonglong2 a3 = xp[3];
        acc[0] = ffma2(a0.x, ww, acc[0]);
        acc[1] = ffma2(a0.y, ww, acc[1]);
        acc[2] = ffma2(a1.x, ww, acc[2]);
        acc[3] = ffma2(a1.y, ww, acc[3]);
        acc[4] = ffma2(a2.x, ww, acc[4]);
        acc[5] = ffma2(a2.y, ww, acc[5]);
        acc[6] = ffma2(a3.x, ww, acc[6]);
        acc[7] = ffma2(a3.y, ww, acc[7]);
    }
}

// ---- 4-row dense accumulate (fused tail kernel) -------------------------------
template <int K0, int K1, int WSTR>
__device__ __forceinline__ void dense4(const float* __restrict__ W,
                                       const float* sIn, int c,
                                       unsigned long long acc[2]) {
    acc[0] = 0ULL; acc[1] = 0ULL;
#pragma unroll 4
    for (int k = K0; k < K1; k++) {
        float w = W[(size_t)k * WSTR + c];
        unsigned long long ww = pk2(w, w);
        ulonglong2 a = *reinterpret_cast<const ulonglong2*>(sIn + k * 4);
        acc[0] = ffma2(a.x, ww, acc[0]);
        acc[1] = ffma2(a.y, ww, acc[1]);
    }
}

// ---------------------------------------------------------------------------
// Prologue: p0 = pMLP(x0), copy x0 -> g_xt, init identity list / counters.
// ---------------------------------------------------------------------------
__global__ __launch_bounds__(NTHR) void sibsde_prologue(
    const float* __restrict__ x0,
    const float* __restrict__ pW1, const float* __restrict__ pb1,
    const float* __restrict__ pW2, const float* __restrict__ pb2,
    const float* __restrict__ pW3, const float* __restrict__ pb3) {
    __shared__ __align__(16) float s_x[D3N * XSTR];
    __shared__ __align__(16) float s_h1[HN * HSTR];
    __shared__ __align__(16) float s_h2[HN * HSTR];

    const int tid = threadIdx.x;
    const int base0 = blockIdx.x * MROWS;

    for (int idx = tid; idx < MROWS * D3N; idx += NTHR) {
        int m = idx / D3N;
        int k = idx - m * D3N;
        float v = x0[(size_t)(base0 + m) * D3N + k];
        g_xt[(size_t)(base0 + m) * D3N + k] = v;
        s_x[k * XSTR + m] = v;
    }
    __syncthreads();

    {   // layer 1: 96 -> 256, tanh
        unsigned long long acc[8];
        dense_acc<0, D3N, XSTR, HN>(pW1, s_x, tid, acc);
        float bv = pb1[tid];
#pragma unroll
        for (int i = 0; i < 8; i++) {
            float u, v; upk2(acc[i], u, v);
            s_h1[tid * HSTR + 2 * i]     = ftanh(u + bv);
            s_h1[tid * HSTR + 2 * i + 1] = ftanh(v + bv);
        }
    }
    __syncthreads();
    {   // layer 2: 256 -> 256, tanh
        unsigned long long acc[8];
        dense_acc<0, HN, HSTR, HN>(pW2, s_h1, tid, acc);
        float bv = pb2[tid];
#pragma unroll
        for (int i = 0; i < 8; i++) {
            float u, v; upk2(acc[i], u, v);
            s_h2[tid * HSTR + 2 * i]     = ftanh(u + bv);
            s_h2[tid * HSTR + 2 * i + 1] = ftanh(v + bv);
        }
    }
    __syncthreads();

    // scalar head: p0[m] = h2[:,m] . pW3 + pb3; warp w handles rows 2w, 2w+1
    const int w = tid >> 5, lane = tid & 31;
#pragma unroll
    for (int r = 0; r < 2; r++) {
        int m = 2 * w + r;
        float s = 0.0f;
#pragma unroll
        for (int j = 0; j < 8; j++) {
            int k = lane + 32 * j;
            s += s_h2[k * HSTR + m] * pW3[k];
        }
#pragma unroll
        for (int o = 16; o > 0; o >>= 1) s += __shfl_xor_sync(0xffffffffu, s, o);
        if (lane == 0) g_p[base0 + m] = s + pb3[0];
    }

    if (tid < MROWS) g_list[0][base0 + tid] = base0 + tid;
    if (blockIdx.x == 0 && tid < 32) g_wcnt[tid] = (tid == 0) ? BN : 0;
}

// ---------------------------------------------------------------------------
// Step 0 (full batch): 16-row tiles, reads checkpoint cpin, writes cpout.
// ---------------------------------------------------------------------------
__global__ __launch_bounds__(NTHR) void sibsde_step16(
    int t, int cpin, int cpout,
    const float* __restrict__ dBt, const float* __restrict__ D,
    const float* __restrict__ gW1, const float* __restrict__ gb1,
    const float* __restrict__ gW2, const float* __restrict__ gb2,
    const float* __restrict__ gW3, const float* __restrict__ gb3,
    float* __restrict__ out) {
    __shared__ __align__(16) float s_x[D3N * XSTR];     // reused as layer3 partial-2
    __shared__ __align__(16) float s_h1[HN * HSTR];     // reused as layer3 partial-1
    __shared__ __align__(16) float s_h2[HN * HSTR];
    __shared__ int   s_rows[MROWS];
    __shared__ float s_sD[DXN];

    const int cnt = g_wcnt[cpin];
    const int base0 = blockIdx.x * MROWS;
    if (base0 >= cnt) return;
    const int nact = min(MROWS, cnt - base0);
    const int tid = threadIdx.x;

    if (tid < MROWS) s_rows[tid] = (tid < nact) ? g_list[cpin & 1][base0 + tid] : 0;
    if (tid < DXN)   s_sD[tid] = sqrtf(2.0f * D[tid]) * 0.1f;   // sqrt(2D)*sqrt(dt)
    __syncthreads();

    for (int idx = tid; idx < MROWS * D3N; idx += NTHR) {
        int m = idx / D3N;
        int k = idx - m * D3N;
        float v = (m < nact) ? g_xt[(size_t)s_rows[m] * D3N + k] : 0.0f;
        s_x[k * XSTR + m] = v;
    }
    __syncthreads();

    const float* W1 = gW1 + (size_t)t * D3N * HN;
    const float* b1 = gb1 + (size_t)t * HN;
    const float* W2 = gW2 + (size_t)t * HN * HN;
    const float* b2 = gb2 + (size_t)t * HN;
    const float* W3 = gW3 + (size_t)t * HN * D3N;
    const float* b3 = gb3 + (size_t)t * D3N;

    {   // layer 1
        unsigned long long acc[8];
        dense_acc<0, D3N, XSTR, HN>(W1, s_x, tid, acc);
        float bv = b1[tid];
#pragma unroll
        for (int i = 0; i < 8; i++) {
            float u, v; upk2(acc[i], u, v);
            s_h1[tid * HSTR + 2 * i]     = ftanh(u + bv);
            s_h1[tid * HSTR + 2 * i + 1] = ftanh(v + bv);
        }
    }
    __syncthreads();
    {   // layer 2
        unsigned long long acc[8];
        dense_acc<0, HN, HSTR, HN>(W2, s_h1, tid, acc);
        float bv = b2[tid];
#pragma unroll
        for (int i = 0; i < 8; i++) {
            float u, v; upk2(acc[i], u, v);
            s_h2[tid * HSTR + 2 * i]     = ftanh(u + bv);
            s_h2[tid * HSTR + 2 * i + 1] = ftanh(v + bv);
        }
    }
    __syncthreads();

    // layer 3 (256 -> 96), split-K across two thread groups.
    float* s_g   = s_h1;   // [MROWS][96] compact, overlays dead s_h1
    float* s_pg2 = s_x;    // [MROWS][96] compact, overlays dead s_x
    if (tid < D3N) {
        unsigned long long acc[8];
        dense_acc<0, HN / 2, HSTR, D3N>(W3, s_h2, tid, acc);
        float bv = b3[tid];
#pragma unroll
        for (int i = 0; i < 8; i++) {
            float u, v; upk2(acc[i], u, v);
            s_g[(2 * i) * D3N + tid]     = u + bv;
            s_g[(2 * i + 1) * D3N + tid] = v + bv;
        }
    } else if (tid >= 128 && tid < 128 + D3N) {
        int c = tid - 128;
        unsigned long long acc[8];
        dense_acc<HN / 2, HN, HSTR, D3N>(W3, s_h2, c, acc);
#pragma unroll
        for (int i = 0; i < 8; i++) {
            float u, v; upk2(acc[i], u, v);
            s_pg2[(2 * i) * D3N + c]     = u;
            s_pg2[(2 * i + 1) * D3N + c] = v;
        }
    }
    __syncthreads();

    // geometry + p update: warp w owns rows 2w, 2w+1; lane = sphere point
    const int w = tid >> 5, lane = tid & 31;
#pragma unroll
    for (int r = 0; r < 2; r++) {
        int m = 2 * w + r;
        if (m >= nact) continue;
        int b = s_rows[m];
        float* xr = g_xt + (size_t)b * D3N;
        float x = xr[3 * lane + 0];
        float y = xr[3 * lane + 1];
        float z = xr[3 * lane + 2];

        float zc = fminf(fmaxf(z, -CLIPF), CLIPF);
        float sa = -zc;
        float ca = sqrtf(fmaxf(1.0f - zc * zc, 0.0f));
        float hyp = sqrtf(x * x + y * y);
        float cp, sp;
        if (hyp > 0.0f) { cp = x / hyp; sp = y / hyp; }
        else            { cp = 1.0f;    sp = 0.0f;    }

        float2 dv = reinterpret_cast<const float2*>(dBt)
                        [((size_t)t * BN + b) * DXN + lane];
        float dth = s_sD[lane] * dv.x;
        float dph = s_sD[lane] * dv.y;

        float th = dth + PI_HALF;
        float sth, cth; sincosf(th,  &sth, &cth);
        float sph, cph; sincosf(dph, &sph, &cph);
        float e0  = sth * cph - 1.0f;
        float e1  = sth * sph;
        float e2v = cth;

        float d0 = cp * ca * e0 - sp * e1 + cp * sa * e2v;
        float d1 = sp * ca * e0 + cp * e1 + sp * sa * e2v;
        float d2 = -sa * e0 + ca * e2v;

        float xn = x + d0;
        float yn = y + d1;
        float zn = fabsf(z + d2);

        xr[3 * lane + 0] = xn;
        xr[3 * lane + 1] = yn;
        xr[3 * lane + 2] = zn;

        float g0 = s_g[m * D3N + 3 * lane + 0] + s_pg2[m * D3N + 3 * lane + 0];
        float g1 = s_g[m * D3N + 3 * lane + 1] + s_pg2[m * D3N + 3 * lane + 1];
        float g2 = s_g[m * D3N + 3 * lane + 2] + s_pg2[m * D3N + 3 * lane + 2];
        float r1v = -g0 * sp + g1 * cp;
        float r2v = g0 * cp * sa + g1 * sp * sa + g2 * ca;
        float dpl = -r2v * dth + r1v * dph;
        float xs  = xn + yn + zn;

        unsigned hm = __ballot_sync(0xffffffffu, zn < HIT_EPSF);
#pragma unroll
        for (int o = 16; o > 0; o >>= 1) {
            dpl += __shfl_xor_sync(0xffffffffu, dpl, o);
            xs  += __shfl_xor_sync(0xffffffffu, xs,  o);
        }
        if (lane == 0) {
            float pold = g_p[b];
            float pnew = pold + (-(0.2f * pold) * 0.01f + dpl);
            if (hm) {
                reinterpret_cast<float2*>(out)[b] = make_float2(pnew, xs / 96.0f);
            } else {
                g_p[b] = pnew;
                int pos = atomicAdd(&g_wcnt[cpout], 1);
                g_list[cpout & 1][pos] = b;
            }
        }
    }
}

// ---------------------------------------------------------------------------
// Fused tail window: nsteps steps starting at t0, 4 rows per block, rows kept
// locally in smem across the window; compaction at window end (cp -> cp+1).
// ---------------------------------------------------------------------------
__global__ __launch_bounds__(NTHR) void sibsde_fused(
    int t0, int nsteps, int cp,
    const float* __restrict__ dBt, const float* __restrict__ D,
    const float* __restrict__ gW1, const float* __restrict__ gb1,
    const float* __restrict__ gW2, const float* __restrict__ gb2,
    const float* __restrict__ gW3, const float* __restrict__ gb3,
    float* __restrict__ out) {
    __shared__ __align__(16) float s_x[D3N * 4];     // [k][m], persists window
    __shared__ __align__(16) float s_h1[HN * 4];
    __shared__ __align__(16) float s_h2[HN * 4];
    __shared__ __align__(16) float s_g1[4 * D3N];
    __shared__ __align__(16) float s_g2[4 * D3N];
    __shared__ int   s_rows[4];
    __shared__ float s_p[4];
    __shared__ float s_sD[DXN];
    __shared__ int   s_alive;

    const int cnt = g_wcnt[cp];
    const int base0 = blockIdx.x * 4;
    if (base0 >= cnt) return;
    const int nact = min(4, cnt - base0);
    const int tid = threadIdx.x;

    if (tid < 4) {
        s_rows[tid] = (tid < nact) ? g_list[cp & 1][base0 + tid] : -1;
        if (tid < nact) s_p[tid] = g_p[s_rows[tid]];
        if (tid == 0) s_alive = (1 << nact) - 1;
    }
    if (tid < DXN) s_sD[tid] = sqrtf(2.0f * D[tid]) * 0.1f;
    __syncthreads();

    for (int idx = tid; idx < 4 * D3N; idx += NTHR) {
        int m = idx & 3, k = idx >> 2;
        s_x[k * 4 + m] = (m < nact) ? g_xt[(size_t)s_rows[m] * D3N + k] : 0.0f;
    }
    __syncthreads();

    const int w = tid >> 5, lane = tid & 31;

    for (int s = 0; s < nsteps; s++) {
        const int t = t0 + s;
        const float* W1 = gW1 + (size_t)t * D3N * HN;
        const float* b1 = gb1 + (size_t)t * HN;
        const float* W2 = gW2 + (size_t)t * HN * HN;
        const float* b2 = gb2 + (size_t)t * HN;
        const float* W3 = gW3 + (size_t)t * HN * D3N;
        const float* b3 = gb3 + (size_t)t * D3N;

        {   // layer 1: 96 -> 256, tanh
            unsigned long long acc[2];
            dense4<0, D3N, HN>(W1, s_x, tid, acc);
            float bv = b1[tid];
            float u, v; float4 hv;
            upk2(acc[0], u, v); hv.x = ftanh(u + bv); hv.y = ftanh(v + bv);
            upk2(acc[1], u, v); hv.z = ftanh(u + bv); hv.w = ftanh(v + bv);
            *reinterpret_cast<float4*>(s_h1 + tid * 4) = hv;
        }
        __syncthreads();
        {   // layer 2: 256 -> 256, tanh
            unsigned long long acc[2];
            dense4<0, HN, HN>(W2, s_h1, tid, acc);
            float bv = b2[tid];
            float u, v; float4 hv;
            upk2(acc[0], u, v); hv.x = ftanh(u + bv); hv.y = ftanh(v + bv);
            upk2(acc[1], u, v); hv.z = ftanh(u + bv); hv.w = ftanh(v + bv);
            *reinterpret_cast<float4*>(s_h2 + tid * 4) = hv;
        }
        __syncthreads();
        // layer 3: 256 -> 96, split-K in two thread groups
        if (tid < D3N) {
            unsigned long long acc[2];
            dense4<0, HN / 2, D3N>(W3, s_h2, tid, acc);
            float bv = b3[tid];
            float u, v;
            upk2(acc[0], u, v);
            s_g1[0 * D3N + tid] = u + bv;
            s_g1[1 * D3N + tid] = v + bv;
            upk2(acc[1], u, v);
            s_g1[2 * D3N + tid] = u + bv;
            s_g1[3 * D3N + tid] = v + bv;
        } else if (tid >= 128 && tid < 128 + D3N) {
            int c = tid - 128;
            unsigned long long acc[2];
            dense4<HN / 2, HN, D3N>(W3, s_h2, c, acc);
            float u, v;
            upk2(acc[0], u, v);
            s_g2[0 * D3N + c] = u;
            s_g2[1 * D3N + c] = v;
            upk2(acc[1], u, v);
            s_g2[2 * D3N + c] = u;
            s_g2[3 * D3N + c] = v;
        }
        __syncthreads();

        // geometry + p update: warp w (w<4) owns row w if alive
        int alive = s_alive;
        if (w < 4 && ((alive >> w) & 1)) {
            int b = s_rows[w];
            float x = s_x[(3 * lane + 0) * 4 + w];
            float y = s_x[(3 * lane + 1) * 4 + w];
            float z = s_x[(3 * lane + 2) * 4 + w];

            float zc = fminf(fmaxf(z, -CLIPF), CLIPF);
            float sa = -zc;
            float ca = sqrtf(fmaxf(1.0f - zc * zc, 0.0f));
            float hyp = sqrtf(x * x + y * y);
            float cpv, spv;
            if (hyp > 0.0f) { cpv = x / hyp; spv = y / hyp; }
            else            { cpv = 1.0f;    spv = 0.0f;    }

            float2 dv = reinterpret_cast<const float2*>(dBt)
                            [((size_t)t * BN + b) * DXN + lane];
            float dth = s_sD[lane] * dv.x;
            float dph = s_sD[lane] * dv.y;

            float th = dth + PI_HALF;
            float sth, cth; sincosf(th,  &sth, &cth);
            float sph, cph; sincosf(dph, &sph, &cph);
            float e0  = sth * cph - 1.0f;
            float e1  = sth * sph;
            float e2v = cth;

            float d0 = cpv * ca * e0 - spv * e1 + cpv * sa * e2v;
            float d1 = spv * ca * e0 + cpv * e1 + spv * sa * e2v;
            float d2 = -sa * e0 + ca * e2v;

            float xn = x + d0;
            float yn = y + d1;
            float zn = fabsf(z + d2);

            s_x[(3 * lane + 0) * 4 + w] = xn;
            s_x[(3 * lane + 1) * 4 + w] = yn;
            s_x[(3 * lane + 2) * 4 + w] = zn;

            float g0 = s_g1[w * D3N + 3 * lane + 0] + s_g2[w * D3N + 3 * lane + 0];
            float g1 = s_g1[w * D3N + 3 * lane + 1] + s_g2[w * D3N + 3 * lane + 1];
            float g2 = s_g1[w * D3N + 3 * lane + 2] + s_g2[w * D3N + 3 * lane + 2];
            float r1v = -g0 * spv + g1 * cpv;
            float r2v = g0 * cpv * sa + g1 * spv * sa + g2 * ca;
            float dpl = -r2v * dth + r1v * dph;
            float xs  = xn + yn + zn;

            unsigned hm = __ballot_sync(0xffffffffu, zn < HIT_EPSF);
#pragma unroll
            for (int o = 16; o > 0; o >>= 1) {
                dpl += __shfl_xor_sync(0xffffffffu, dpl, o);
                xs  += __shfl_xor_sync(0xffffffffu, xs,  o);
            }
            if (lane == 0) {
                float pold = s_p[w];
                float pnew = pold + (-(0.2f * pold) * 0.01f + dpl);
                if (hm) {
                    reinterpret_cast<float2*>(out)[b] = make_float2(pnew, xs / 96.0f);
                    atomicAnd(&s_alive, ~(1 << w));
                } else {
                    s_p[w] = pnew;
                }
            }
        }
        __syncthreads();
        if (s_alive == 0) break;    // uniform: read after barrier
    }

    // window end: write back survivors, append to next checkpoint
    int alive = s_alive;
    if (alive) {
        for (int idx = tid; idx < 4 * D3N; idx += NTHR) {
            int m = idx & 3, k = idx >> 2;
            if ((alive >> m) & 1)
                g_xt[(size_t)s_rows[m] * D3N + k] = s_x[k * 4 + m];
        }
        if (tid < 4 && ((alive >> tid) & 1)) {
            g_p[s_rows[tid]] = s_p[tid];
            int pos = atomicAdd(&g_wcnt[cp + 1], 1);
            g_list[(cp + 1) & 1][pos] = s_rows[tid];
        }
    }
}

// ---------------------------------------------------------------------------
// Epilogue: rows still running after 100 steps -> out = {p, mean(xt)}.
// ---------------------------------------------------------------------------
__global__ __launch_bounds__(NTHR) void sibsde_epilogue(float* __restrict__ out,
                                                        int cpF) {
    const int cnt = g_wcnt[cpF];
    const int wi = (blockIdx.x * NTHR + threadIdx.x) >> 5;
    const int lane = threadIdx.x & 31;
    if (wi >= cnt) return;
    int b = g_list[cpF & 1][wi];
    const float* xr = g_xt + (size_t)b * D3N;
    float s = xr[lane] + xr[lane + 32] + xr[lane + 64];
#pragma unroll
    for (int o = 16; o > 0; o >>= 1) s += __shfl_xor_sync(0xffffffffu, s, o);
    if (lane == 0)
        reinterpret_cast<float2*>(out)[b] = make_float2(g_p[b], s / 96.0f);
}

// ---------------------------------------------------------------------------
extern "C" void kernel_launch(void* const* d_in, const int* in_sizes, int n_in,
                              void* d_out, int out_size) {
    const float* x0  = (const float*)d_in[0];
    const float* dBt = (const float*)d_in[1];
    const float* D   = (const float*)d_in[2];
    const float* pW1 = (const float*)d_in[3];
    const float* pb1 = (const float*)d_in[4];
    const float* pW2 = (const float*)d_in[5];
    const float* pb2 = (const float*)d_in[6];
    const float* pW3 = (const float*)d_in[7];
    const float* pb3 = (const float*)d_in[8];
    const float* gW1 = (const float*)d_in[9];
    const float* gb1 = (const float*)d_in[10];
    const float* gW2 = (const float*)d_in[11];
    const float* gb2 = (const float*)d_in[12];
    const float* gW3 = (const float*)d_in[13];
    const float* gb3 = (const float*)d_in[14];
    float* out = (float*)d_out;

    sibsde_prologue<<<NBLK, NTHR>>>(x0, pW1, pb1, pW2, pb2, pW3, pb3);
    // step 0 on the full batch: 16-row tiles, checkpoint 0 -> 1
    sibsde_step16<<<NBLK, NTHR>>>(0, 0, 1, dBt, D, gW1, gb1, gW2, gb2, gW3, gb3, out);

    // fused tail windows: sizes 1, 2, 4, then 8s (15 windows, cp 1..16)
    int cp = 1, pos = 1;
    while (pos < NSTEPN) {
        int S;
        if      (pos == 1) S = 1;
        else if (pos == 2) S = 2;
        else if (pos == 4) S = 4;
        else               S = (NSTEPN - pos < 8) ? (NSTEPN - pos) : 8;
        sibsde_fused<<<BN / 4, NTHR>>>(pos, S, cp, dBt, D,
                                       gW1, gb1, gW2, gb2, gW3, gb3, out);
        pos += S; cp++;
    }
    sibsde_epilogue<<<BN * 32 / NTHR, NTHR>>>(out, cp);
}

// round 9
// speedup vs baseline: 1.9876x; 1.2952x over previous
#include <cuda_runtime.h>
#include <math.h>

// ---------------------------------------------------------------------------
// SphereIBSDE: 100-step sphere SDE with per-step MLP (96->256->256->96).
// Step 0: full batch, 16-row tiles. Steps 1..99: fused windows of 4-row
// blocks with local row retention; global compaction at window boundaries.
// R9: MLP-16 weight loads + 4-way k-interleaved accumulators (latency fix).
// ---------------------------------------------------------------------------

#define BN      4096
#define DXN     32
#define D3N     96
#define NSTEPN  100
#define HN      256
#define MROWS   16
#define NBLK    (BN / MROWS)       // 256
#define NTHR    256
#define XSTR    16                 // step16 s_x stride
#define HSTR    20                 // step16 hidden stride
#define HIT_EPSF 0.05f
#define CLIPF   (1.0f - 1e-6f)
#define PI_HALF 1.57079632679489662f

// persistent scratch (static device globals; no allocation)
__device__ float g_xt[BN * D3N];
__device__ float g_p[BN];
__device__ int   g_list[2][BN];
__device__ int   g_wcnt[32];       // checkpoint counters (17 used)

// ---- packed f32x2 helpers ---------------------------------------------------
__device__ __forceinline__ unsigned long long pk2(float x, float y) {
    unsigned long long r;
    asm("mov.b64 %0, {%1, %2};" : "=l"(r) : "f"(x), "f"(y));
    return r;
}
__device__ __forceinline__ void upk2(unsigned long long v, float& x, float& y) {
    asm("mov.b64 {%0, %1}, %2;" : "=f"(x), "=f"(y) : "l"(v));
}
__device__ __forceinline__ unsigned long long ffma2(unsigned long long a,
                                                    unsigned long long b,
                                                    unsigned long long c) {
    unsigned long long d;
    asm("fma.rn.f32x2 %0, %1, %2, %3;" : "=l"(d) : "l"(a), "l"(b), "l"(c));
    return d;
}
__device__ __forceinline__ unsigned long long add2(unsigned long long a,
                                                   unsigned long long b) {
    unsigned long long d;
    asm("add.rn.f32x2 %0, %1, %2;" : "=l"(d) : "l"(a), "l"(b));
    return d;
}

// fast tanh: only feeds p (never the xt / hit path), so approx is safe.
__device__ __forceinline__ float ftanh(float x) {
    float e = __expf(2.0f * x);
    return 1.0f - __fdividef(2.0f, e + 1.0f);
}

// ---- 16-row dense accumulate (step0 / prologue): MLP-8 -----------------------
template <int K0, int K1, int INSTR, int WSTR>
__device__ __forceinline__ void dense_acc(const float* __restrict__ W,
                                          const float* sIn, int c,
                                          unsigned long long acc[8]) {
#pragma unroll
    for (int i = 0; i < 8; i++) acc[i] = 0ULL;
    const float* Wc = W + c;
#pragma unroll 8
    for (int k = K0; k < K1; k++) {
        float w = Wc[(size_t)k * WSTR];
        unsigned long long ww = pk2(w, w);
        const ulonglong2* xp = reinterpret_cast<const ulonglong2*>(sIn + k * INSTR);
        ulonglong2 a0 = xp[0];
        ulonglong2 a1 = xp[1];
        ulonglong2 a2 = xp[2];
        ulonglong2 a3 = xp[3];
        acc[0] = ffma2(a0.x, ww, acc[0]);
        acc[1] = ffma2(a0.y, ww, acc[1]);
        acc[2] = ffma2(a1.x, ww, acc[2]);
        acc[3] = ffma2(a1.y, ww, acc[3]);
        acc[4] = ffma2(a2.x, ww, acc[4]);
        acc[5] = ffma2(a2.y, ww, acc[5]);
        acc[6] = ffma2(a3.x, ww, acc[6]);
        acc[7] = ffma2(a3.y, ww, acc[7]);
    }
}

// ---- 4-row dense accumulate (fused tail): MLP-16, 4 independent FMA chains --
// (K1-K0) must be a multiple of 16 (96, 128, 256 all qualify).
template <int K0, int K1, int WSTR>
__device__ __forceinline__ void dense4(const float* __restrict__ W,
                                       const float* sIn, int c,
                                       unsigned long long acc[2]) {
    unsigned long long p0 = 0, p1 = 0, q0 = 0, q1 = 0;
    unsigned long long r0 = 0, r1 = 0, s0 = 0, s1 = 0;
    const float* Wc = W + c;
#pragma unroll 4
    for (int k = K0; k < K1; k += 4) {
        float w0 = Wc[(size_t)(k + 0) * WSTR];
        float w1 = Wc[(size_t)(k + 1) * WSTR];
        float w2 = Wc[(size_t)(k + 2) * WSTR];
        float w3 = Wc[(size_t)(k + 3) * WSTR];
        ulonglong2 a0 = *reinterpret_cast<const ulonglong2*>(sIn + (k + 0) * 4);
        ulonglong2 a1 = *reinterpret_cast<const ulonglong2*>(sIn + (k + 1) * 4);
        ulonglong2 a2 = *reinterpret_cast<const ulonglong2*>(sIn + (k + 2) * 4);
        ulonglong2 a3 = *reinterpret_cast<const ulonglong2*>(sIn + (k + 3) * 4);
        unsigned long long ww0 = pk2(w0, w0);
        unsigned long long ww1 = pk2(w1, w1);
        unsigned long long ww2 = pk2(w2, w2);
        unsigned long long ww3 = pk2(w3, w3);
        p0 = ffma2(a0.x, ww0, p0); p1 = ffma2(a0.y, ww0, p1);
        q0 = ffma2(a1.x, ww1, q0); q1 = ffma2(a1.y, ww1, q1);
        r0 = ffma2(a2.x, ww2, r0); r1 = ffma2(a2.y, ww2, r1);
        s0 = ffma2(a3.x, ww3, s0); s1 = ffma2(a3.y, ww3, s1);
    }
    acc[0] = add2(add2(p0, q0), add2(r0, s0));
    acc[1] = add2(add2(p1, q1), add2(r1, s1));
}

// ---------------------------------------------------------------------------
// Prologue: p0 = pMLP(x0), copy x0 -> g_xt, init identity list / counters.
// ---------------------------------------------------------------------------
__global__ __launch_bounds__(NTHR) void sibsde_prologue(
    const float* __restrict__ x0,
    const float* __restrict__ pW1, const float* __restrict__ pb1,
    const float* __restrict__ pW2, const float* __restrict__ pb2,
    const float* __restrict__ pW3, const float* __restrict__ pb3) {
    __shared__ __align__(16) float s_x[D3N * XSTR];
    __shared__ __align__(16) float s_h1[HN * HSTR];
    __shared__ __align__(16) float s_h2[HN * HSTR];

    const int tid = threadIdx.x;
    const int base0 = blockIdx.x * MROWS;

    for (int idx = tid; idx < MROWS * D3N; idx += NTHR) {
        int m = idx / D3N;
        int k = idx - m * D3N;
        float v = x0[(size_t)(base0 + m) * D3N + k];
        g_xt[(size_t)(base0 + m) * D3N + k] = v;
        s_x[k * XSTR + m] = v;
    }
    __syncthreads();

    {   // layer 1: 96 -> 256, tanh
        unsigned long long acc[8];
        dense_acc<0, D3N, XSTR, HN>(pW1, s_x, tid, acc);
        float bv = pb1[tid];
#pragma unroll
        for (int i = 0; i < 8; i++) {
            float u, v; upk2(acc[i], u, v);
            s_h1[tid * HSTR + 2 * i]     = ftanh(u + bv);
            s_h1[tid * HSTR + 2 * i + 1] = ftanh(v + bv);
        }
    }
    __syncthreads();
    {   // layer 2: 256 -> 256, tanh
        unsigned long long acc[8];
        dense_acc<0, HN, HSTR, HN>(pW2, s_h1, tid, acc);
        float bv = pb2[tid];
#pragma unroll
        for (int i = 0; i < 8; i++) {
            float u, v; upk2(acc[i], u, v);
            s_h2[tid * HSTR + 2 * i]     = ftanh(u + bv);
            s_h2[tid * HSTR + 2 * i + 1] = ftanh(v + bv);
        }
    }
    __syncthreads();

    // scalar head: p0[m] = h2[:,m] . pW3 + pb3; warp w handles rows 2w, 2w+1
    const int w = tid >> 5, lane = tid & 31;
#pragma unroll
    for (int r = 0; r < 2; r++) {
        int m = 2 * w + r;
        float s = 0.0f;
#pragma unroll
        for (int j = 0; j < 8; j++) {
            int k = lane + 32 * j;
            s += s_h2[k * HSTR + m] * pW3[k];
        }
#pragma unroll
        for (int o = 16; o > 0; o >>= 1) s += __shfl_xor_sync(0xffffffffu, s, o);
        if (lane == 0) g_p[base0 + m] = s + pb3[0];
    }

    if (tid < MROWS) g_list[0][base0 + tid] = base0 + tid;
    if (blockIdx.x == 0 && tid < 32) g_wcnt[tid] = (tid == 0) ? BN : 0;
}

// ---------------------------------------------------------------------------
// Step 0 (full batch): 16-row tiles, reads checkpoint cpin, writes cpout.
// ---------------------------------------------------------------------------
__global__ __launch_bounds__(NTHR) void sibsde_step16(
    int t, int cpin, int cpout,
    const float* __restrict__ dBt, const float* __restrict__ D,
    const float* __restrict__ gW1, const float* __restrict__ gb1,
    const float* __restrict__ gW2, const float* __restrict__ gb2,
    const float* __restrict__ gW3, const float* __restrict__ gb3,
    float* __restrict__ out) {
    __shared__ __align__(16) float s_x[D3N * XSTR];     // reused as layer3 partial-2
    __shared__ __align__(16) float s_h1[HN * HSTR];     // reused as layer3 partial-1
    __shared__ __align__(16) float s_h2[HN * HSTR];
    __shared__ int   s_rows[MROWS];
    __shared__ float s_sD[DXN];

    const int cnt = g_wcnt[cpin];
    const int base0 = blockIdx.x * MROWS;
    if (base0 >= cnt) return;
    const int nact = min(MROWS, cnt - base0);
    const int tid = threadIdx.x;

    if (tid < MROWS) s_rows[tid] = (tid < nact) ? g_list[cpin & 1][base0 + tid] : 0;
    if (tid < DXN)   s_sD[tid] = sqrtf(2.0f * D[tid]) * 0.1f;   // sqrt(2D)*sqrt(dt)
    __syncthreads();

    for (int idx = tid; idx < MROWS * D3N; idx += NTHR) {
        int m = idx / D3N;
        int k = idx - m * D3N;
        float v = (m < nact) ? g_xt[(size_t)s_rows[m] * D3N + k] : 0.0f;
        s_x[k * XSTR + m] = v;
    }
    __syncthreads();

    const float* W1 = gW1 + (size_t)t * D3N * HN;
    const float* b1 = gb1 + (size_t)t * HN;
    const float* W2 = gW2 + (size_t)t * HN * HN;
    const float* b2 = gb2 + (size_t)t * HN;
    const float* W3 = gW3 + (size_t)t * HN * D3N;
    const float* b3 = gb3 + (size_t)t * D3N;

    {   // layer 1
        unsigned long long acc[8];
        dense_acc<0, D3N, XSTR, HN>(W1, s_x, tid, acc);
        float bv = b1[tid];
#pragma unroll
        for (int i = 0; i < 8; i++) {
            float u, v; upk2(acc[i], u, v);
            s_h1[tid * HSTR + 2 * i]     = ftanh(u + bv);
            s_h1[tid * HSTR + 2 * i + 1] = ftanh(v + bv);
        }
    }
    __syncthreads();
    {   // layer 2
        unsigned long long acc[8];
        dense_acc<0, HN, HSTR, HN>(W2, s_h1, tid, acc);
        float bv = b2[tid];
#pragma unroll
        for (int i = 0; i < 8; i++) {
            float u, v; upk2(acc[i], u, v);
            s_h2[tid * HSTR + 2 * i]     = ftanh(u + bv);
            s_h2[tid * HSTR + 2 * i + 1] = ftanh(v + bv);
        }
    }
    __syncthreads();

    // layer 3 (256 -> 96), split-K across two thread groups.
    float* s_g   = s_h1;   // [MROWS][96] compact, overlays dead s_h1
    float* s_pg2 = s_x;    // [MROWS][96] compact, overlays dead s_x
    if (tid < D3N) {
        unsigned long long acc[8];
        dense_acc<0, HN / 2, HSTR, D3N>(W3, s_h2, tid, acc);
        float bv = b3[tid];
#pragma unroll
        for (int i = 0; i < 8; i++) {
            float u, v; upk2(acc[i], u, v);
            s_g[(2 * i) * D3N + tid]     = u + bv;
            s_g[(2 * i + 1) * D3N + tid] = v + bv;
        }
    } else if (tid >= 128 && tid < 128 + D3N) {
        int c = tid - 128;
        unsigned long long acc[8];
        dense_acc<HN / 2, HN, HSTR, D3N>(W3, s_h2, c, acc);
#pragma unroll
        for (int i = 0; i < 8; i++) {
            float u, v; upk2(acc[i], u, v);
            s_pg2[(2 * i) * D3N + c]     = u;
            s_pg2[(2 * i + 1) * D3N + c] = v;
        }
    }
    __syncthreads();

    // geometry + p update: warp w owns rows 2w, 2w+1; lane = sphere point
    const int w = tid >> 5, lane = tid & 31;
#pragma unroll
    for (int r = 0; r < 2; r++) {
        int m = 2 * w + r;
        if (m >= nact) continue;
        int b = s_rows[m];
        float* xr = g_xt + (size_t)b * D3N;
        float x = xr[3 * lane + 0];
        float y = xr[3 * lane + 1];
        float z = xr[3 * lane + 2];

        float zc = fminf(fmaxf(z, -CLIPF), CLIPF);
        float sa = -zc;
        float ca = sqrtf(fmaxf(1.0f - zc * zc, 0.0f));
        float hyp = sqrtf(x * x + y * y);
        float cp, sp;
        if (hyp > 0.0f) { cp = x / hyp; sp = y / hyp; }
        else            { cp = 1.0f;    sp = 0.0f;    }

        float2 dv = reinterpret_cast<const float2*>(dBt)
                        [((size_t)t * BN + b) * DXN + lane];
        float dth = s_sD[lane] * dv.x;
        float dph = s_sD[lane] * dv.y;

        float th = dth + PI_HALF;
        float sth, cth; sincosf(th,  &sth, &cth);
        float sph, cph; sincosf(dph, &sph, &cph);
        float e0  = sth * cph - 1.0f;
        float e1  = sth * sph;
        float e2v = cth;

        float d0 = cp * ca * e0 - sp * e1 + cp * sa * e2v;
        float d1 = sp * ca * e0 + cp * e1 + sp * sa * e2v;
        float d2 = -sa * e0 + ca * e2v;

        float xn = x + d0;
        float yn = y + d1;
        float zn = fabsf(z + d2);

        xr[3 * lane + 0] = xn;
        xr[3 * lane + 1] = yn;
        xr[3 * lane + 2] = zn;

        float g0 = s_g[m * D3N + 3 * lane + 0] + s_pg2[m * D3N + 3 * lane + 0];
        float g1 = s_g[m * D3N + 3 * lane + 1] + s_pg2[m * D3N + 3 * lane + 1];
        float g2 = s_g[m * D3N + 3 * lane + 2] + s_pg2[m * D3N + 3 * lane + 2];
        float r1v = -g0 * sp + g1 * cp;
        float r2v = g0 * cp * sa + g1 * sp * sa + g2 * ca;
        float dpl = -r2v * dth + r1v * dph;
        float xs  = xn + yn + zn;

        unsigned hm = __ballot_sync(0xffffffffu, zn < HIT_EPSF);
#pragma unroll
        for (int o = 16; o > 0; o >>= 1) {
            dpl += __shfl_xor_sync(0xffffffffu, dpl, o);
            xs  += __shfl_xor_sync(0xffffffffu, xs,  o);
        }
        if (lane == 0) {
            float pold = g_p[b];
            float pnew = pold + (-(0.2f * pold) * 0.01f + dpl);
            if (hm) {
                reinterpret_cast<float2*>(out)[b] = make_float2(pnew, xs / 96.0f);
            } else {
                g_p[b] = pnew;
                int pos = atomicAdd(&g_wcnt[cpout], 1);
                g_list[cpout & 1][pos] = b;
            }
        }
    }
}

// ---------------------------------------------------------------------------
// Fused tail window: nsteps steps starting at t0, 4 rows per block, rows kept
// locally in smem across the window; compaction at window end (cp -> cp+1).
// ---------------------------------------------------------------------------
__global__ __launch_bounds__(NTHR) void sibsde_fused(
    int t0, int nsteps, int cp,
    const float* __restrict__ dBt, const float* __restrict__ D,
    const float* __restrict__ gW1, const float* __restrict__ gb1,
    const float* __restrict__ gW2, const float* __restrict__ gb2,
    const float* __restrict__ gW3, const float* __restrict__ gb3,
    float* __restrict__ out) {
    __shared__ __align__(16) float s_x[D3N * 4];     // [k][m], persists window
    __shared__ __align__(16) float s_h1[HN * 4];
    __shared__ __align__(16) float s_h2[HN * 4];
    __shared__ __align__(16) float s_g1[4 * D3N];
    __shared__ __align__(16) float s_g2[4 * D3N];
    __shared__ int   s_rows[4];
    __shared__ float s_p[4];
    __shared__ float s_sD[DXN];
    __shared__ int   s_alive;

    const int cnt = g_wcnt[cp];
    const int base0 = blockIdx.x * 4;
    if (base0 >= cnt) return;
    const int nact = min(4, cnt - base0);
    const int tid = threadIdx.x;

    if (tid < 4) {
        s_rows[tid] = (tid < nact) ? g_list[cp & 1][base0 + tid] : -1;
        if (tid < nact) s_p[tid] = g_p[s_rows[tid]];
        if (tid == 0) s_alive = (1 << nact) - 1;
    }
    if (tid < DXN) s_sD[tid] = sqrtf(2.0f * D[tid]) * 0.1f;
    __syncthreads();

    for (int idx = tid; idx < 4 * D3N; idx += NTHR) {
        int m = idx & 3, k = idx >> 2;
        s_x[k * 4 + m] = (m < nact) ? g_xt[(size_t)s_rows[m] * D3N + k] : 0.0f;
    }
    __syncthreads();

    const int w = tid >> 5, lane = tid & 31;

    for (int s = 0; s < nsteps; s++) {
        const int t = t0 + s;
        const float* W1 = gW1 + (size_t)t * D3N * HN;
        const float* b1 = gb1 + (size_t)t * HN;
        const float* W2 = gW2 + (size_t)t * HN * HN;
        const float* b2 = gb2 + (size_t)t * HN;
        const float* W3 = gW3 + (size_t)t * HN * D3N;
        const float* b3 = gb3 + (size_t)t * D3N;

        {   // layer 1: 96 -> 256, tanh
            unsigned long long acc[2];
            dense4<0, D3N, HN>(W1, s_x, tid, acc);
            float bv = b1[tid];
            float u, v; float4 hv;
            upk2(acc[0], u, v); hv.x = ftanh(u + bv); hv.y = ftanh(v + bv);
            upk2(acc[1], u, v); hv.z = ftanh(u + bv); hv.w = ftanh(v + bv);
            *reinterpret_cast<float4*>(s_h1 + tid * 4) = hv;
        }
        __syncthreads();
        {   // layer 2: 256 -> 256, tanh
            unsigned long long acc[2];
            dense4<0, HN, HN>(W2, s_h1, tid, acc);
            float bv = b2[tid];
            float u, v; float4 hv;
            upk2(acc[0], u, v); hv.x = ftanh(u + bv); hv.y = ftanh(v + bv);
            upk2(acc[1], u, v); hv.z = ftanh(u + bv); hv.w = ftanh(v + bv);
            *reinterpret_cast<float4*>(s_h2 + tid * 4) = hv;
        }
        __syncthreads();
        // layer 3: 256 -> 96, split-K in two thread groups
        if (tid < D3N) {
            unsigned long long acc[2];
            dense4<0, HN / 2, D3N>(W3, s_h2, tid, acc);
            float bv = b3[tid];
            float u, v;
            upk2(acc[0], u, v);
            s_g1[0 * D3N + tid] = u + bv;
            s_g1[1 * D3N + tid] = v + bv;
            upk2(acc[1], u, v);
            s_g1[2 * D3N + tid] = u + bv;
            s_g1[3 * D3N + tid] = v + bv;
        } else if (tid >= 128 && tid < 128 + D3N) {
            int c = tid - 128;
            unsigned long long acc[2];
            dense4<HN / 2, HN, D3N>(W3, s_h2, c, acc);
            float u, v;
            upk2(acc[0], u, v);
            s_g2[0 * D3N + c] = u;
            s_g2[1 * D3N + c] = v;
            upk2(acc[1], u, v);
            s_g2[2 * D3N + c] = u;
            s_g2[3 * D3N + c] = v;
        }
        __syncthreads();

        // geometry + p update: warp w (w<4) owns row w if alive
        int alive = s_alive;
        if (w < 4 && ((alive >> w) & 1)) {
            int b = s_rows[w];
            float x = s_x[(3 * lane + 0) * 4 + w];
            float y = s_x[(3 * lane + 1) * 4 + w];
            float z = s_x[(3 * lane + 2) * 4 + w];

            float zc = fminf(fmaxf(z, -CLIPF), CLIPF);
            float sa = -zc;
            float ca = sqrtf(fmaxf(1.0f - zc * zc, 0.0f));
            float hyp = sqrtf(x * x + y * y);
            float cpv, spv;
            if (hyp > 0.0f) { cpv = x / hyp; spv = y / hyp; }
            else            { cpv = 1.0f;    spv = 0.0f;    }

            float2 dv = reinterpret_cast<const float2*>(dBt)
                            [((size_t)t * BN + b) * DXN + lane];
            float dth = s_sD[lane] * dv.x;
            float dph = s_sD[lane] * dv.y;

            float th = dth + PI_HALF;
            float sth, cth; sincosf(th,  &sth, &cth);
            float sph, cph; sincosf(dph, &sph, &cph);
            float e0  = sth * cph - 1.0f;
            float e1  = sth * sph;
            float e2v = cth;

            float d0 = cpv * ca * e0 - spv * e1 + cpv * sa * e2v;
            float d1 = spv * ca * e0 + cpv * e1 + spv * sa * e2v;
            float d2 = -sa * e0 + ca * e2v;

            float xn = x + d0;
            float yn = y + d1;
            float zn = fabsf(z + d2);

            s_x[(3 * lane + 0) * 4 + w] = xn;
            s_x[(3 * lane + 1) * 4 + w] = yn;
            s_x[(3 * lane + 2) * 4 + w] = zn;

            float g0 = s_g1[w * D3N + 3 * lane + 0] + s_g2[w * D3N + 3 * lane + 0];
            float g1 = s_g1[w * D3N + 3 * lane + 1] + s_g2[w * D3N + 3 * lane + 1];
            float g2 = s_g1[w * D3N + 3 * lane + 2] + s_g2[w * D3N + 3 * lane + 2];
            float r1v = -g0 * spv + g1 * cpv;
            float r2v = g0 * cpv * sa + g1 * spv * sa + g2 * ca;
            float dpl = -r2v * dth + r1v * dph;
            float xs  = xn + yn + zn;

            unsigned hm = __ballot_sync(0xffffffffu, zn < HIT_EPSF);
#pragma unroll
            for (int o = 16; o > 0; o >>= 1) {
                dpl += __shfl_xor_sync(0xffffffffu, dpl, o);
                xs  += __shfl_xor_sync(0xffffffffu, xs,  o);
            }
            if (lane == 0) {
                float pold = s_p[w];
                float pnew = pold + (-(0.2f * pold) * 0.01f + dpl);
                if (hm) {
                    reinterpret_cast<float2*>(out)[b] = make_float2(pnew, xs / 96.0f);
                    atomicAnd(&s_alive, ~(1 << w));
                } else {
                    s_p[w] = pnew;
                }
            }
        }
        __syncthreads();
        if (s_alive == 0) break;    // uniform: read after barrier
    }

    // window end: write back survivors, append to next checkpoint
    int alive = s_alive;
    if (alive) {
        for (int idx = tid; idx < 4 * D3N; idx += NTHR) {
            int m = idx & 3, k = idx >> 2;
            if ((alive >> m) & 1)
                g_xt[(size_t)s_rows[m] * D3N + k] = s_x[k * 4 + m];
        }
        if (tid < 4 && ((alive >> tid) & 1)) {
            g_p[s_rows[tid]] = s_p[tid];
            int pos = atomicAdd(&g_wcnt[cp + 1], 1);
            g_list[(cp + 1) & 1][pos] = s_rows[tid];
        }
    }
}

// ---------------------------------------------------------------------------
// Epilogue: rows still running after 100 steps -> out = {p, mean(xt)}.
// ---------------------------------------------------------------------------
__global__ __launch_bounds__(NTHR) void sibsde_epilogue(float* __restrict__ out,
                                                        int cpF) {
    const int cnt = g_wcnt[cpF];
    const int wi = (blockIdx.x * NTHR + threadIdx.x) >> 5;
    const int lane = threadIdx.x & 31;
    if (wi >= cnt) return;
    int b = g_list[cpF & 1][wi];
    const float* xr = g_xt + (size_t)b * D3N;
    float s = xr[lane] + xr[lane + 32] + xr[lane + 64];
#pragma unroll
    for (int o = 16; o > 0; o >>= 1) s += __shfl_xor_sync(0xffffffffu, s, o);
    if (lane == 0)
        reinterpret_cast<float2*>(out)[b] = make_float2(g_p[b], s / 96.0f);
}

// ---------------------------------------------------------------------------
extern "C" void kernel_launch(void* const* d_in, const int* in_sizes, int n_in,
                              void* d_out, int out_size) {
    const float* x0  = (const float*)d_in[0];
    const float* dBt = (const float*)d_in[1];
    const float* D   = (const float*)d_in[2];
    const float* pW1 = (const float*)d_in[3];
    const float* pb1 = (const float*)d_in[4];
    const float* pW2 = (const float*)d_in[5];
    const float* pb2 = (const float*)d_in[6];
    const float* pW3 = (const float*)d_in[7];
    const float* pb3 = (const float*)d_in[8];
    const float* gW1 = (const float*)d_in[9];
    const float* gb1 = (const float*)d_in[10];
    const float* gW2 = (const float*)d_in[11];
    const float* gb2 = (const float*)d_in[12];
    const float* gW3 = (const float*)d_in[13];
    const float* gb3 = (const float*)d_in[14];
    float* out = (float*)d_out;

    sibsde_prologue<<<NBLK, NTHR>>>(x0, pW1, pb1, pW2, pb2, pW3, pb3);
    // step 0 on the full batch: 16-row tiles, checkpoint 0 -> 1
    sibsde_step16<<<NBLK, NTHR>>>(0, 0, 1, dBt, D, gW1, gb1, gW2, gb2, gW3, gb3, out);

    // fused tail windows: sizes 1, 2, 4, then 8s (15 windows, cp 1..16)
    int cp = 1, pos = 1;
    while (pos < NSTEPN) {
        int S;
        if      (pos == 1) S = 1;
        else if (pos == 2) S = 2;
        else if (pos == 4) S = 4;
        else               S = (NSTEPN - pos < 8) ? (NSTEPN - pos) : 8;
        sibsde_fused<<<BN / 4, NTHR>>>(pos, S, cp, dBt, D,
                                       gW1, gb1, gW2, gb2, gW3, gb3, out);
        pos += S; cp++;
    }
    sibsde_epilogue<<<BN * 32 / NTHR, NTHR>>>(out, cp);
}